// round 5
// baseline (speedup 1.0000x reference)
#include <cuda_runtime.h>
#include <cstdint>
#include <cstddef>

#define S_LEN 2048
#define B_DIM 64
#define I_DIM 512
#define H_DIM 512
#define G_DIM 2048  // 4*H

// ---------------- scratch (static device globals) -------------------------------
__device__ __align__(16) float g_xw[(size_t)S_LEN * B_DIM * G_DIM];   // 1 GB
__device__ __align__(16) float g_h[2][B_DIM * H_DIM];
__device__ __align__(16) unsigned long long g_flags[128 * 16];  // 128B-strided flags

// ---------------- packed f32x2 helpers ------------------------------------------
__device__ __forceinline__ unsigned long long pk2(float lo, float hi) {
    unsigned long long r;
    asm("mov.b64 %0, {%1, %2};" : "=l"(r) : "f"(lo), "f"(hi));
    return r;
}
__device__ __forceinline__ void upk2(unsigned long long v, float& lo, float& hi) {
    asm("mov.b64 {%0, %1}, %2;" : "=f"(lo), "=f"(hi) : "l"(v));
}
__device__ __forceinline__ void ffma2(unsigned long long& d, unsigned long long a, unsigned long long b) {
    asm("fma.rn.f32x2 %0, %1, %2, %0;" : "+l"(d) : "l"(a), "l"(b));
}
// MUFU-based activations (abs err ~1e-6; far inside the 1e-3 budget)
__device__ __forceinline__ float sigmoid_f(float x) {
    return __fdividef(1.0f, 1.0f + __expf(-x));
}
__device__ __forceinline__ float tanh_f(float x) {
    float e = __expf(2.0f * x);
    return 1.0f - __fdividef(2.0f, e + 1.0f);
}
// ---------------- release/acquire flag ops --------------------------------------
__device__ __forceinline__ void st_release_gpu(unsigned long long* p, unsigned long long v) {
    asm volatile("st.release.gpu.u64 [%0], %1;" :: "l"(p), "l"(v) : "memory");
}
__device__ __forceinline__ unsigned long long ld_acquire_gpu(const unsigned long long* p) {
    unsigned long long v;
    asm volatile("ld.acquire.gpu.u64 %0, [%1];" : "=l"(v) : "l"(p) : "memory");
    return v;
}
// ---------------- cp.async ------------------------------------------------------
__device__ __forceinline__ void cp_async16(uint32_t dst_smem, const void* src) {
    asm volatile("cp.async.cg.shared.global [%0], [%1], 16;"
                 :: "r"(dst_smem), "l"(src) : "memory");
}
__device__ __forceinline__ void cp_commit() {
    asm volatile("cp.async.commit_group;" ::: "memory");
}
template <int N>
__device__ __forceinline__ void cp_wait() {
    asm volatile("cp.async.wait_group %0;" :: "n"(N) : "memory");
}

// =====================================================================
// Kernel 1: xW = x @ W + bias (near its f32x2 issue floor; stcs epilogue)
// =====================================================================
__global__ __launch_bounds__(256, 2) void gemm_xw_kernel(
    const float* __restrict__ x, const float* __restrict__ W,
    const float* __restrict__ bias)
{
    __shared__ float As[8][128];
    __shared__ float Bs[8][128];

    const int t  = threadIdx.x;
    const int m0 = blockIdx.y * 128;
    const int n0 = blockIdx.x * 128;
    const int tx = t & 15;
    const int ty = t >> 4;

    const int arow = t >> 1, akc = (t & 1) * 4;
    const int brow = t >> 5, bnc = (t & 31) * 4;

    unsigned long long acc[8][4];
    #pragma unroll
    for (int m = 0; m < 8; m++)
        #pragma unroll
        for (int n = 0; n < 4; n++) acc[m][n] = 0ULL;

    float4 av = *(const float4*)(x + (size_t)(m0 + arow) * I_DIM + akc);
    float4 bv = *(const float4*)(W + (size_t)brow * G_DIM + n0 + bnc);

    for (int kt = 0; kt < 64; kt++) {
        __syncthreads();
        As[akc + 0][arow] = av.x;
        As[akc + 1][arow] = av.y;
        As[akc + 2][arow] = av.z;
        As[akc + 3][arow] = av.w;
        *(float4*)&Bs[brow][bnc] = bv;
        __syncthreads();
        if (kt < 63) {
            av = *(const float4*)(x + (size_t)(m0 + arow) * I_DIM + (kt + 1) * 8 + akc);
            bv = *(const float4*)(W + (size_t)((kt + 1) * 8 + brow) * G_DIM + n0 + bnc);
        }
        #pragma unroll
        for (int kk = 0; kk < 8; kk++) {
            float4 a01 = *(const float4*)&As[kk][ty * 8];
            float4 a23 = *(const float4*)&As[kk][ty * 8 + 4];
            ulonglong2 b01 = *(const ulonglong2*)&Bs[kk][tx * 8];
            ulonglong2 b23 = *(const ulonglong2*)&Bs[kk][tx * 8 + 4];
            float am[8] = {a01.x, a01.y, a01.z, a01.w, a23.x, a23.y, a23.z, a23.w};
            #pragma unroll
            for (int m = 0; m < 8; m++) {
                unsigned long long aa = pk2(am[m], am[m]);
                ffma2(acc[m][0], aa, b01.x);
                ffma2(acc[m][1], aa, b01.y);
                ffma2(acc[m][2], aa, b23.x);
                ffma2(acc[m][3], aa, b23.y);
            }
        }
    }

    float bb[8];
    #pragma unroll
    for (int i = 0; i < 8; i++) bb[i] = bias[n0 + tx * 8 + i];
    #pragma unroll
    for (int m = 0; m < 8; m++) {
        float c[8];
        upk2(acc[m][0], c[0], c[1]);
        upk2(acc[m][1], c[2], c[3]);
        upk2(acc[m][2], c[4], c[5]);
        upk2(acc[m][3], c[6], c[7]);
        #pragma unroll
        for (int i = 0; i < 8; i++) c[i] += bb[i];
        float* op = g_xw + (size_t)(m0 + ty * 8 + m) * G_DIM + n0 + tx * 8;
        __stcs((float4*)op,       make_float4(c[0], c[1], c[2], c[3]));
        __stcs((float4*)(op + 4), make_float4(c[4], c[5], c[6], c[7]));
    }
}

// =====================================================================
// Kernel 2: persistent recurrence. 128 thr/CTA, grid (64,2) = 128 CTAs.
// CTA (j,bq): batches [bq*32,+32), h-cols [j*8,+8).
// Thread t: col hc=t&7, batches b0=2*(t>>3), b0+1; computes all 4 gates
// of its own 2 cells -> zero gate exchange.
// U_s[kq][4 quads][8 cols][4 k] pitch 128 fl; h_s[kq][32 b][4 k] pitch 132 fl.
// h tile streamed via cp.async in 4 chunks, overlapped with FMA chunks.
// =====================================================================
#define NQ     128
#define UPITCH 128
#define HPITCH 132
#define CH_UB  (32 * UPITCH * 4)   // chunk stride in U_s, bytes
#define CH_HB  (32 * HPITCH * 4)   // chunk stride in h_s, bytes
#define SMEM_FLOATS (NQ * UPITCH + NQ * HPITCH)
#define SMEM_BYTES  (SMEM_FLOATS * 4)

__device__ __forceinline__ void chunk_fma(const char* up, const char* hp,
                                          unsigned long long (&acc)[4][2])
{
    #pragma unroll 2
    for (int kq = 0; kq < 32; kq++) {
        ulonglong2 u0 = *(const ulonglong2*)(up);
        ulonglong2 u1 = *(const ulonglong2*)(up + 128);
        ulonglong2 u2 = *(const ulonglong2*)(up + 256);
        ulonglong2 u3 = *(const ulonglong2*)(up + 384);
        ulonglong2 h0 = *(const ulonglong2*)(hp);
        ulonglong2 h1 = *(const ulonglong2*)(hp + 16);
        ffma2(acc[0][0], h0.x, u0.x); ffma2(acc[0][0], h0.y, u0.y);
        ffma2(acc[0][1], h1.x, u0.x); ffma2(acc[0][1], h1.y, u0.y);
        ffma2(acc[1][0], h0.x, u1.x); ffma2(acc[1][0], h0.y, u1.y);
        ffma2(acc[1][1], h1.x, u1.x); ffma2(acc[1][1], h1.y, u1.y);
        ffma2(acc[2][0], h0.x, u2.x); ffma2(acc[2][0], h0.y, u2.y);
        ffma2(acc[2][1], h1.x, u2.x); ffma2(acc[2][1], h1.y, u2.y);
        ffma2(acc[3][0], h0.x, u3.x); ffma2(acc[3][0], h0.y, u3.y);
        ffma2(acc[3][1], h1.x, u3.x); ffma2(acc[3][1], h1.y, u3.y);
        up += UPITCH * 4;
        hp += HPITCH * 4;
    }
}

__global__ __launch_bounds__(128, 1) void lstm_rec_kernel(
    const float* __restrict__ U, float* __restrict__ out, size_t out_size)
{
    extern __shared__ float sm[];
    float* U_s = sm;                      // [128][128]
    float* h_s = sm + NQ * UPITCH;        // [128][132]

    const int t   = threadIdx.x;          // 0..127
    const int j   = blockIdx.x;           // 0..63
    const int bq  = blockIdx.y;           // 0..1
    const int cta = bq * 64 + j;          // 0..127

    const int hc = t & 7;                 // col within slice
    const int b0 = (t >> 3) * 2;          // local batch pair
    const int col  = j * 8 + hc;
    const int gb0  = bq * 32 + b0;

    // ---- U slice load: U_s[kq][c][ki] <- U[k][(c>>3)*512 + j*8 + (c&7)]
    for (int idx = t; idx < 512 * 32; idx += 128) {
        int k = idx >> 5;
        int c = idx & 31;
        float v = U[(size_t)k * G_DIM + (c >> 3) * H_DIM + j * 8 + (c & 7)];
        U_s[(k >> 2) * UPITCH + c * 4 + (k & 3)] = v;
    }

    // ---- zero h_buf[0]
    g_h[0][cta * 256 + t]       = 0.0f;
    g_h[0][cta * 256 + 128 + t] = 0.0f;

    unsigned long long base = ld_acquire_gpu(&g_flags[cta * 16]);

    // init barrier
    __syncthreads();
    if (t == 0) st_release_gpu(&g_flags[cta * 16], base + 1);
    {
        const unsigned long long* f = &g_flags[t * 16];
        int spins = 0;
        while (ld_acquire_gpu(f) < base + 1) { if (++spins > 16) __nanosleep(64); }
    }
    __syncthreads();

    const uint32_t hs_u32 = (uint32_t)__cvta_generic_to_shared(h_s);
    float cA = 0.0f, cB = 0.0f;

    for (int ts = 0; ts < S_LEN; ts++) {
        const int cur = ts & 1, nxt = cur ^ 1;

        // ---- xW prefetch (independent of barrier; hides DRAM latency)
        float xw[4][2];
        {
            const float* xb = g_xw + ((size_t)ts * B_DIM + gb0) * G_DIM + j * 8 + hc;
            #pragma unroll
            for (int q = 0; q < 4; q++) {
                xw[q][0] = __ldcs(xb + q * H_DIM);
                xw[q][1] = __ldcs(xb + q * H_DIM + G_DIM);
            }
        }

        // ---- wait for previous step's h
        if (ts > 0) {
            unsigned long long tgt = base + 1 + (unsigned long long)ts;
            const unsigned long long* f = &g_flags[t * 16];
            int spins = 0;
            while (ld_acquire_gpu(f) < tgt) { if (++spins > 16) __nanosleep(64); }
            __syncthreads();
        }

        // ---- issue h tile as 4 cp.async chunks (global-coalesced mapping)
        {
            const float* hb = g_h[cur] + (size_t)bq * 32 * H_DIM;
            #pragma unroll
            for (int g = 0; g < 4; g++) {
                #pragma unroll
                for (int n = 0; n < 8; n++) {
                    int idx = n * 128 + t;        // 0..1023
                    int b   = idx >> 5;           // 0..31 (same for all lanes of a warp)
                    int kql = idx & 31;
                    int kq  = g * 32 + kql;
                    cp_async16(hs_u32 + (uint32_t)(kq * HPITCH + b * 4) * 4,
                               hb + (size_t)b * H_DIM + kq * 4);
                }
                cp_commit();
            }
        }

        // ---- chunked compute, overlapped with in-flight cp.async chunks
        unsigned long long acc[4][2];
        #pragma unroll
        for (int q = 0; q < 4; q++) { acc[q][0] = 0ULL; acc[q][1] = 0ULL; }

        const char* ub = (const char*)U_s + hc * 16;
        const char* hb = (const char*)h_s + b0 * 16;
        cp_wait<3>(); __syncthreads(); chunk_fma(ub,            hb,            acc);
        cp_wait<2>(); __syncthreads(); chunk_fma(ub + CH_UB,    hb + CH_HB,    acc);
        cp_wait<1>(); __syncthreads(); chunk_fma(ub + 2*CH_UB,  hb + 2*CH_HB,  acc);
        cp_wait<0>(); __syncthreads(); chunk_fma(ub + 3*CH_UB,  hb + 3*CH_HB,  acc);

        // ---- gates -> cell update entirely in registers
        float s[4][2];
        #pragma unroll
        for (int q = 0; q < 4; q++) {
            float l, h_;
            upk2(acc[q][0], l, h_); s[q][0] = l + h_ + xw[q][0];
            upk2(acc[q][1], l, h_); s[q][1] = l + h_ + xw[q][1];
        }
        float iA = sigmoid_f(s[0][0]), fA = sigmoid_f(s[1][0]);
        float gA = tanh_f(s[2][0]),    oA = sigmoid_f(s[3][0]);
        float iB = sigmoid_f(s[0][1]), fB = sigmoid_f(s[1][1]);
        float gB = tanh_f(s[2][1]),    oB = sigmoid_f(s[3][1]);

        cA = fA * cA + iA * gA;
        cB = fB * cB + iB * gB;
        float hA = oA * tanh_f(cA);
        float hB = oB * tanh_f(cB);

        // ---- h store (critical), then release, then out stores (off-path)
        __stcg(&g_h[nxt][(gb0)     * H_DIM + col], hA);
        __stcg(&g_h[nxt][(gb0 + 1) * H_DIM + col], hB);
        __syncthreads();
        if (ts < S_LEN - 1 && t == 0)
            st_release_gpu(&g_flags[cta * 16], base + 2 + (unsigned long long)ts);

        float* ob = out + (size_t)ts * (B_DIM * H_DIM);
        __stcs(&ob[(gb0)     * H_DIM + col], hA);
        __stcs(&ob[(gb0 + 1) * H_DIM + col], hB);

        if (ts == S_LEN - 1) {
            const size_t SEQ  = (size_t)S_LEN * B_DIM * H_DIM;
            const size_t need = SEQ + 2 * (size_t)B_DIM * H_DIM;
            if (out_size >= need) {
                out[SEQ + (gb0)     * H_DIM + col]                         = hA;
                out[SEQ + (gb0 + 1) * H_DIM + col]                         = hB;
                out[SEQ + (size_t)B_DIM * H_DIM + (gb0)     * H_DIM + col] = cA;
                out[SEQ + (size_t)B_DIM * H_DIM + (gb0 + 1) * H_DIM + col] = cB;
            }
        }
    }
}

// =====================================================================
extern "C" void kernel_launch(void* const* d_in, const int* in_sizes, int n_in,
                              void* d_out, int out_size) {
    const float* x    = (const float*)d_in[0];
    const float* W    = (const float*)d_in[1];
    const float* U    = (const float*)d_in[2];
    const float* bias = (const float*)d_in[3];
    float* out = (float*)d_out;
    (void)in_sizes; (void)n_in;

    cudaFuncSetAttribute(lstm_rec_kernel,
                         cudaFuncAttributeMaxDynamicSharedMemorySize, SMEM_BYTES);

    dim3 ggrid(G_DIM / 128, (S_LEN * B_DIM) / 128);  // (16, 1024)
    gemm_xw_kernel<<<ggrid, 256>>>(x, W, bias);

    dim3 rgrid(64, 2);  // 128 CTAs, 1 per SM (smem-limited) -> all co-resident
    lstm_rec_kernel<<<rgrid, 128, SMEM_BYTES>>>(U, out, (size_t)out_size);
}

// round 6
// speedup vs baseline: 1.1539x; 1.1539x over previous
#include <cuda_runtime.h>
#include <cstdint>
#include <cstddef>

#define S_LEN 2048
#define B_DIM 64
#define I_DIM 512
#define H_DIM 512
#define G_DIM 2048  // 4*H

// ---------------- scratch (static device globals) -------------------------------
__device__ __align__(16) float g_xw[(size_t)S_LEN * B_DIM * G_DIM];   // 1 GB
__device__ __align__(16) float g_h[2][B_DIM * H_DIM];
__device__ __align__(16) unsigned long long g_flags[128 * 16];  // 128B-strided flags

// ---------------- packed f32x2 helpers ------------------------------------------
__device__ __forceinline__ unsigned long long pk2(float lo, float hi) {
    unsigned long long r;
    asm("mov.b64 %0, {%1, %2};" : "=l"(r) : "f"(lo), "f"(hi));
    return r;
}
__device__ __forceinline__ void upk2(unsigned long long v, float& lo, float& hi) {
    asm("mov.b64 {%0, %1}, %2;" : "=f"(lo), "=f"(hi) : "l"(v));
}
__device__ __forceinline__ void ffma2(unsigned long long& d, unsigned long long a, unsigned long long b) {
    asm("fma.rn.f32x2 %0, %1, %2, %0;" : "+l"(d) : "l"(a), "l"(b));
}
// MUFU-based activations (abs err ~1e-6, far inside 1e-3 budget)
__device__ __forceinline__ float sigmoid_f(float x) {
    return __fdividef(1.0f, 1.0f + __expf(-x));
}
__device__ __forceinline__ float tanh_f(float x) {
    float e = __expf(2.0f * x);
    return 1.0f - __fdividef(2.0f, e + 1.0f);
}
// ---------------- release/acquire flag ops --------------------------------------
__device__ __forceinline__ void st_release_gpu(unsigned long long* p, unsigned long long v) {
    asm volatile("st.release.gpu.u64 [%0], %1;" :: "l"(p), "l"(v) : "memory");
}
__device__ __forceinline__ unsigned long long ld_acquire_gpu(const unsigned long long* p) {
    unsigned long long v;
    asm volatile("ld.acquire.gpu.u64 %0, [%1];" : "=l"(v) : "l"(p) : "memory");
    return v;
}

// =====================================================================
// Kernel 1: xW = x @ W + bias (unchanged — at its f32x2 issue floor)
// =====================================================================
__global__ __launch_bounds__(256, 2) void gemm_xw_kernel(
    const float* __restrict__ x, const float* __restrict__ W,
    const float* __restrict__ bias)
{
    __shared__ float As[8][128];
    __shared__ float Bs[8][128];

    const int t  = threadIdx.x;
    const int m0 = blockIdx.y * 128;
    const int n0 = blockIdx.x * 128;
    const int tx = t & 15;
    const int ty = t >> 4;

    const int arow = t >> 1, akc = (t & 1) * 4;
    const int brow = t >> 5, bnc = (t & 31) * 4;

    unsigned long long acc[8][4];
    #pragma unroll
    for (int m = 0; m < 8; m++)
        #pragma unroll
        for (int n = 0; n < 4; n++) acc[m][n] = 0ULL;

    float4 av = *(const float4*)(x + (size_t)(m0 + arow) * I_DIM + akc);
    float4 bv = *(const float4*)(W + (size_t)brow * G_DIM + n0 + bnc);

    for (int kt = 0; kt < 64; kt++) {
        __syncthreads();
        As[akc + 0][arow] = av.x;
        As[akc + 1][arow] = av.y;
        As[akc + 2][arow] = av.z;
        As[akc + 3][arow] = av.w;
        *(float4*)&Bs[brow][bnc] = bv;
        __syncthreads();
        if (kt < 63) {
            av = *(const float4*)(x + (size_t)(m0 + arow) * I_DIM + (kt + 1) * 8 + akc);
            bv = *(const float4*)(W + (size_t)((kt + 1) * 8 + brow) * G_DIM + n0 + bnc);
        }
        #pragma unroll
        for (int kk = 0; kk < 8; kk++) {
            float4 a01 = *(const float4*)&As[kk][ty * 8];
            float4 a23 = *(const float4*)&As[kk][ty * 8 + 4];
            ulonglong2 b01 = *(const ulonglong2*)&Bs[kk][tx * 8];
            ulonglong2 b23 = *(const ulonglong2*)&Bs[kk][tx * 8 + 4];
            float am[8] = {a01.x, a01.y, a01.z, a01.w, a23.x, a23.y, a23.z, a23.w};
            #pragma unroll
            for (int m = 0; m < 8; m++) {
                unsigned long long aa = pk2(am[m], am[m]);
                ffma2(acc[m][0], aa, b01.x);
                ffma2(acc[m][1], aa, b01.y);
                ffma2(acc[m][2], aa, b23.x);
                ffma2(acc[m][3], aa, b23.y);
            }
        }
    }

    float bb[8];
    #pragma unroll
    for (int i = 0; i < 8; i++) bb[i] = bias[n0 + tx * 8 + i];
    #pragma unroll
    for (int m = 0; m < 8; m++) {
        float c[8];
        upk2(acc[m][0], c[0], c[1]);
        upk2(acc[m][1], c[2], c[3]);
        upk2(acc[m][2], c[4], c[5]);
        upk2(acc[m][3], c[6], c[7]);
        #pragma unroll
        for (int i = 0; i < 8; i++) c[i] += bb[i];
        float* op = g_xw + (size_t)(m0 + ty * 8 + m) * G_DIM + n0 + tx * 8;
        __stcs((float4*)op,       make_float4(c[0], c[1], c[2], c[3]));
        __stcs((float4*)(op + 4), make_float4(c[4], c[5], c[6], c[7]));
    }
}

// =====================================================================
// Kernel 2: persistent recurrence. 128 thr/CTA, grid (64,2) = 128 CTAs.
// TWO independent 64-CTA barrier domains (one per batch half bq).
// CTA (j,bq): batches [bq*32,+32), h-cols [j*8,+8).
// Thread: col hc=t&7, batches b0=2*(t>>3), b0+1; computes all 4 gates of
// its own 2 cells (no gate exchange).
// U_s[kq][4 gate quads x 8 cols][4 k]  pitch 128 floats.
// h_s[b][512 k] pitch 516 floats: STS contiguous, LDS broadcast, 0 conflicts.
// =====================================================================
#define NQ     128
#define UPITCH 128
#define KPITCH 516
#define SMEM_FLOATS (NQ * UPITCH + 32 * KPITCH)
#define SMEM_BYTES  (SMEM_FLOATS * 4)

__global__ __launch_bounds__(128, 1) void lstm_rec_kernel(
    const float* __restrict__ U, float* __restrict__ out, size_t out_size)
{
    extern __shared__ float sm[];
    float* U_s = sm;                      // [128][128]
    float* h_s = sm + NQ * UPITCH;        // [32][516]

    const int t   = threadIdx.x;          // 0..127
    const int j   = blockIdx.x;           // 0..63
    const int bq  = blockIdx.y;           // 0..1  (barrier domain)
    const int cta = bq * 64 + j;

    const int hc = t & 7;
    const int b0 = (t >> 3) * 2;
    const int col = j * 8 + hc;
    const int gb0 = bq * 32 + b0;

    unsigned long long* dom_flags = g_flags + (size_t)bq * 64 * 16;

    // ---- U slice load: U_s[kq][q*8+hc][ki] <- U[k][q*512 + j*8 + hc]
    for (int idx = t; idx < 512 * 32; idx += 128) {
        int k = idx >> 5;
        int c = idx & 31;
        float v = U[(size_t)k * G_DIM + (c >> 3) * H_DIM + j * 8 + (c & 7)];
        U_s[(k >> 2) * UPITCH + c * 4 + (k & 3)] = v;
    }

    // ---- zero h_buf[0] (this domain's half: 64 CTAs x 512 floats = 32x512)
    {
        float* hz = g_h[0] + (size_t)bq * 32 * H_DIM;
        hz[j * 256 + t]       = 0.0f;
        hz[j * 256 + 128 + t] = 0.0f;
    }

    unsigned long long base = ld_acquire_gpu(&dom_flags[j * 16]);

    // init barrier (domain-local)
    __syncthreads();
    if (t == 0) st_release_gpu(&dom_flags[j * 16], base + 1);
    if (t < 64) {
        const unsigned long long* f = &dom_flags[t * 16];
        while (ld_acquire_gpu(f) < base + 1) {}
    }
    __syncthreads();

    float cA = 0.0f, cB = 0.0f;

    for (int ts = 0; ts < S_LEN; ts++) {
        const int cur = ts & 1, nxt = cur ^ 1;

        // ---- xW prefetch (independent of barrier; hides DRAM latency)
        float xw[4][2];
        {
            const float* xb = g_xw + ((size_t)ts * B_DIM + gb0) * G_DIM + j * 8 + hc;
            #pragma unroll
            for (int q = 0; q < 4; q++) {
                xw[q][0] = __ldcs(xb + q * H_DIM);
                xw[q][1] = __ldcs(xb + q * H_DIM + G_DIM);
            }
        }

        // ---- wait for previous step's h (domain-local, hard spin)
        if (ts > 0) {
            unsigned long long tgt = base + 1 + (unsigned long long)ts;
            if (t < 64) {
                const unsigned long long* f = &dom_flags[t * 16];
                while (ld_acquire_gpu(f) < tgt) {}
            }
            __syncthreads();
        }

        // ---- h tile load: iter n = batch n; thread t covers 512 floats/row.
        //      STS contiguous (conflict-free), global coalesced (2KB/iter).
        {
            const float* hb = g_h[cur] + (size_t)bq * 32 * H_DIM;
            #pragma unroll 8
            for (int n = 0; n < 32; n++) {
                float4 v = __ldcg((const float4*)(hb + n * H_DIM + t * 4));
                *(float4*)&h_s[n * KPITCH + t * 4] = v;
            }
        }
        __syncthreads();

        // ---- gates = h @ U  (k-packed f32x2; 4 gates x 2 batches per thread)
        unsigned long long acc[4][2];
        #pragma unroll
        for (int q = 0; q < 4; q++) { acc[q][0] = 0ULL; acc[q][1] = 0ULL; }

        const char* up = (const char*)(U_s + hc * 4);
        const char* hp = (const char*)(h_s + b0 * KPITCH);
        #pragma unroll 4
        for (int kq = 0; kq < NQ; kq++) {
            ulonglong2 u0 = *(const ulonglong2*)(up);
            ulonglong2 u1 = *(const ulonglong2*)(up + 128);
            ulonglong2 u2 = *(const ulonglong2*)(up + 256);
            ulonglong2 u3 = *(const ulonglong2*)(up + 384);
            ulonglong2 h0 = *(const ulonglong2*)(hp);
            ulonglong2 h1 = *(const ulonglong2*)(hp + KPITCH * 4);
            ffma2(acc[0][0], h0.x, u0.x); ffma2(acc[0][0], h0.y, u0.y);
            ffma2(acc[0][1], h1.x, u0.x); ffma2(acc[0][1], h1.y, u0.y);
            ffma2(acc[1][0], h0.x, u1.x); ffma2(acc[1][0], h0.y, u1.y);
            ffma2(acc[1][1], h1.x, u1.x); ffma2(acc[1][1], h1.y, u1.y);
            ffma2(acc[2][0], h0.x, u2.x); ffma2(acc[2][0], h0.y, u2.y);
            ffma2(acc[2][1], h1.x, u2.x); ffma2(acc[2][1], h1.y, u2.y);
            ffma2(acc[3][0], h0.x, u3.x); ffma2(acc[3][0], h0.y, u3.y);
            ffma2(acc[3][1], h1.x, u3.x); ffma2(acc[3][1], h1.y, u3.y);
            up += UPITCH * 4;
            hp += 16;
        }

        // ---- gates -> cell update entirely in registers
        float s[4][2];
        #pragma unroll
        for (int q = 0; q < 4; q++) {
            float l, h_;
            upk2(acc[q][0], l, h_); s[q][0] = l + h_ + xw[q][0];
            upk2(acc[q][1], l, h_); s[q][1] = l + h_ + xw[q][1];
        }
        float iA = sigmoid_f(s[0][0]), fA = sigmoid_f(s[1][0]);
        float gA = tanh_f(s[2][0]),    oA = sigmoid_f(s[3][0]);
        float iB = sigmoid_f(s[0][1]), fB = sigmoid_f(s[1][1]);
        float gB = tanh_f(s[2][1]),    oB = sigmoid_f(s[3][1]);

        cA = fA * cA + iA * gA;
        cB = fB * cB + iB * gB;
        float hA = oA * tanh_f(cA);
        float hB = oB * tanh_f(cB);

        // ---- h store (critical), release, then out stores (off-path)
        __stcg(&g_h[nxt][(gb0)     * H_DIM + col], hA);
        __stcg(&g_h[nxt][(gb0 + 1) * H_DIM + col], hB);
        __syncthreads();
        if (ts < S_LEN - 1 && t == 0)
            st_release_gpu(&dom_flags[j * 16], base + 2 + (unsigned long long)ts);

        float* ob = out + (size_t)ts * (B_DIM * H_DIM);
        __stcs(&ob[(gb0)     * H_DIM + col], hA);
        __stcs(&ob[(gb0 + 1) * H_DIM + col], hB);

        if (ts == S_LEN - 1) {
            const size_t SEQ  = (size_t)S_LEN * B_DIM * H_DIM;
            const size_t need = SEQ + 2 * (size_t)B_DIM * H_DIM;
            if (out_size >= need) {
                out[SEQ + (gb0)     * H_DIM + col]                         = hA;
                out[SEQ + (gb0 + 1) * H_DIM + col]                         = hB;
                out[SEQ + (size_t)B_DIM * H_DIM + (gb0)     * H_DIM + col] = cA;
                out[SEQ + (size_t)B_DIM * H_DIM + (gb0 + 1) * H_DIM + col] = cB;
            }
        }
    }
}

// =====================================================================
extern "C" void kernel_launch(void* const* d_in, const int* in_sizes, int n_in,
                              void* d_out, int out_size) {
    const float* x    = (const float*)d_in[0];
    const float* W    = (const float*)d_in[1];
    const float* U    = (const float*)d_in[2];
    const float* bias = (const float*)d_in[3];
    float* out = (float*)d_out;
    (void)in_sizes; (void)n_in;

    cudaFuncSetAttribute(lstm_rec_kernel,
                         cudaFuncAttributeMaxDynamicSharedMemorySize, SMEM_BYTES);

    dim3 ggrid(G_DIM / 128, (S_LEN * B_DIM) / 128);  // (16, 1024)
    gemm_xw_kernel<<<ggrid, 256>>>(x, W, bias);

    dim3 rgrid(64, 2);  // 128 CTAs, 1/SM (smem-limited) -> all co-resident
    lstm_rec_kernel<<<rgrid, 128, SMEM_BYTES>>>(U, out, (size_t)out_size);
}